// round 11
// baseline (speedup 1.0000x reference)
#include <cuda_runtime.h>
#include <cuda_fp16.h>
#include <math.h>

#define BB 4
#define NN 8192
#define FF 64
#define H1 64
#define H2 32
#define K2P 40            // padded half2 pairs per W1 row (67 inputs + bias + pad to 2x20)
#define TPB 256           // threads per CTA
#define PPC 128           // points per CTA (2 lanes per point)
#define CPB 64            // chunks (CTAs) per batch = 8192/128

__device__ __forceinline__ __half2 u2h2(unsigned int u) {
    return *reinterpret_cast<__half2*>(&u);
}

// ---- scratch (static, no allocation) ----
__device__ float g_csum[BB * CPB];
__device__ float g_csq[BB * CPB];
__device__ int   g_ccnt[BB * CPB];     // selected (>0.7) per chunk
__device__ int   g_cmask[BB * CPB];    // mask count per chunk
__device__ int   g_sel[BB][NN];        // per-chunk compacted selected indices (128 slots/chunk)
__device__ int   g_selc[BB][NN];       // globally compacted selected indices
__device__ int   g_done[BB];           // zero-initialized; reset after each use

// ============================================================
// Single kernel: K-split pair-lane MLP 67 -> 64 -> 32 -> 1 (+mask).
// Lane parity s: even handles K-pairs [0,20), odd [20,40) — loads,
// conversions, weight LDS and passthrough stores all split (no dup).
// h1 combined per 8-output group via shfl_xor; layer 2 split by output
// half; layer 3 split by K + one shfl. Fused stats/compaction epilogue
// + last-CTA-per-batch finalize with global scratch (smem ~15KB).
// ============================================================
__global__ __launch_bounds__(TPB) void mlp_kernel(
    const float* __restrict__ points, const float* __restrict__ features,
    const int* __restrict__ mask,
    const float* __restrict__ W1, const float* __restrict__ b1,
    const float* __restrict__ W2, const float* __restrict__ b2,
    const float* __restrict__ W3, const float* __restrict__ b3,
    float* __restrict__ scores, float* __restrict__ out_feats,
    float* __restrict__ conf_out)
{
    __shared__ __align__(16) __half2 sW1h[H1][K2P];   // 64*40*4 = 10240B
    __shared__ __align__(16) __half2 sW2h[H2][H1/2];  // 4096B
    __shared__ float sW3[H2];
    __shared__ float sb2[H2];
    __shared__ float sb3;
    __shared__ float rsum[8], rsq[8];
    __shared__ int rcnt[8], rmask[8], roff[8];
    // finalize-only (small)
    __shared__ int cpref[CPB], ccnt_s[CPB];
    __shared__ int segoff[2];
    __shared__ float f_sum, f_sq;
    __shared__ int f_cnt, f_nleaf, s_last;
    __shared__ float wsd[8], wsd2[8];
    __shared__ float swsum[2], swsq[2];
    __shared__ int swm[2], swtot[2];

    int tid = threadIdx.x;
    int lane = tid & 31, warp = tid >> 5;
    int s = tid & 1;                  // K-half: 0 => pairs [0,20), 1 => [20,40)

    // ---- pack W1 (+bias1) into half2 [64][40] ----
    for (int idx = tid; idx < H1 * K2P; idx += TPB) {
        int j = idx / K2P, k2 = idx % K2P;
        float a = 0.f, bv = 0.f;
        if (k2 <= 33) {
            int k = 2 * k2;
            a  = (k     < 67) ? W1[j * 67 + k]     : 0.f;
            bv = (k + 1 < 67) ? W1[j * 67 + k + 1] : 0.f;
        } else if (k2 == 34) {
            a = b1[j];                 // bias slot, x pair 34 = (1, 0)
        }
        sW1h[j][k2] = __floats2half2_rn(a, bv);
    }
    // ---- pack W2 into half2 [32][32] ----
    for (int idx = tid; idx < H2 * (H1 / 2); idx += TPB) {
        int i = idx / (H1 / 2), j2 = idx % (H1 / 2);
        sW2h[i][j2] = __floats2half2_rn(W2[i * H1 + 2 * j2], W2[i * H1 + 2 * j2 + 1]);
    }
    if (tid < H2) { sb2[tid] = b2[tid]; sW3[tid] = W3[tid]; }
    if (tid == 0) sb3 = b3[0];
    __syncthreads();

    int p = blockIdx.x * PPC + (tid >> 1);   // point id, two lanes per point
    int fb = p >> 13;                        // batch

    // ---- split input load + passthrough + fp16 pack ----
    // local x2[k] = global K-pair s*20 + k
    __half2 x2[20];
    const float4* f4 = (const float4*)(features + (size_t)p * FF);
    float4* o4 = (float4*)(out_feats + (size_t)p * FF);
    if (s == 0) {
        // global pairs 0..19 = features[0..39] = f4 i 0..9
#pragma unroll
        for (int i = 0; i < 10; i++) {
            float4 v = f4[i];
            o4[i] = v;
            x2[2 * i]     = __floats2half2_rn(v.x, v.y);
            x2[2 * i + 1] = __floats2half2_rn(v.z, v.w);
        }
    } else {
        // global pairs 20..31 = features[40..63] = f4 i 10..15
#pragma unroll
        for (int i = 10; i < 16; i++) {
            float4 v = f4[i];
            o4[i] = v;
            x2[2 * (i - 10)]     = __floats2half2_rn(v.x, v.y);
            x2[2 * (i - 10) + 1] = __floats2half2_rn(v.z, v.w);
        }
        const float* pp = points + (size_t)p * 3;
        x2[12] = __floats2half2_rn(pp[0], pp[1]);   // global pair 32
        x2[13] = __floats2half2_rn(pp[2], 0.f);     // 33
        x2[14] = __floats2half2_rn(1.f, 0.f);       // 34 bias
        x2[15] = __floats2half2_rn(0.f, 0.f);
        x2[16] = __floats2half2_rn(0.f, 0.f);
        x2[17] = __floats2half2_rn(0.f, 0.f);
        x2[18] = __floats2half2_rn(0.f, 0.f);
        x2[19] = __floats2half2_rn(0.f, 0.f);
    }

    // ---- layer-2 partial accumulators: this lane owns h2 rows [s*16, s*16+16) ----
    __half2 h2acc[16];
#pragma unroll
    for (int i = 0; i < 16; i++)
        h2acc[i] = __floats2half2_rn(sb2[s * 16 + i], 0.f);

    const int wq = s * 5;               // this lane's uint4 offset in W1 rows
    const int w2row = s * 16;           // this lane's W2 row base

    // ---- layer 1: 8 groups of 8 outputs; each lane does its K-half ----
    for (int jg = 0; jg < H1 / 8; jg++) {
        float h[8];
#pragma unroll
        for (int jj = 0; jj < 8; jj++) {
            const uint4* row = reinterpret_cast<const uint4*>(sW1h[jg * 8 + jj]) + wq;
            __half2 aa = __floats2half2_rn(0.f, 0.f);
            __half2 ab = __floats2half2_rn(0.f, 0.f);
#pragma unroll
            for (int q = 0; q < 5; q++) {
                uint4 w = row[q];
                aa = __hfma2(u2h2(w.x), x2[4 * q],     aa);
                ab = __hfma2(u2h2(w.y), x2[4 * q + 1], ab);
                aa = __hfma2(u2h2(w.z), x2[4 * q + 2], aa);
                ab = __hfma2(u2h2(w.w), x2[4 * q + 3], ab);
            }
            float2 f = __half22float2(__hadd2(aa, ab));
            h[jj] = f.x + f.y;          // partial (this K-half), no relu yet
        }
        // pack partials, exchange with partner lane, add, relu
        __half2 hp[4];
#pragma unroll
        for (int t = 0; t < 4; t++) {
            __half2 mine = __floats2half2_rn(h[2 * t], h[2 * t + 1]);
            unsigned int mu = *reinterpret_cast<unsigned int*>(&mine);
            unsigned int ou = __shfl_xor_sync(0xFFFFFFFFu, mu, 1);
            __half2 tot = __hadd2(mine, u2h2(ou));
            hp[t] = __hmax2(tot, __floats2half2_rn(0.f, 0.f));
        }

        // fold 8 fresh h1 values into this lane's 16 h2 rows
#pragma unroll
        for (int i = 0; i < 16; i++) {
            uint4 w = reinterpret_cast<const uint4*>(sW2h[w2row + i])[jg];
            h2acc[i] = __hfma2(u2h2(w.x), hp[0], h2acc[i]);
            h2acc[i] = __hfma2(u2h2(w.y), hp[1], h2acc[i]);
            h2acc[i] = __hfma2(u2h2(w.z), hp[2], h2acc[i]);
            h2acc[i] = __hfma2(u2h2(w.w), hp[3], h2acc[i]);
        }
    }

    // ---- layer 3 (fp32): this lane's 16 h2 rows, then pair combine ----
    float z0 = 0.f, z1 = 0.f;
#pragma unroll
    for (int i = 0; i < 16; i += 2) {
        float2 f0 = __half22float2(h2acc[i]);
        float2 f1 = __half22float2(h2acc[i + 1]);
        z0 += sW3[w2row + i]     * fmaxf(f0.x + f0.y, 0.f);
        z1 += sW3[w2row + i + 1] * fmaxf(f1.x + f1.y, 0.f);
    }
    float zp = z0 + z1;
    float z = sb3 + zp + __shfl_xor_sync(0xFFFFFFFFu, zp, 1);  // commutative add
    float sv = 1.0f / (1.0f + expf(-z));

    int m = mask[p];
    float score = (m != 0) ? sv : 0.0f;
    if (s == 0) scores[p] = score;

    // ---------- fused stats + compaction epilogue (even lanes own points) ----------
    bool selp = (s == 0) && (score > 0.7f);
    unsigned int bal = __ballot_sync(0xFFFFFFFFu, selp);
    int wcnt = __popc(bal);
    int myoff = __popc(bal & ((1u << lane) - 1u));

    float csc = (s == 0) ? score : 0.0f;
    float sum = csc, sq = csc * csc;
    int mc = (s == 0 && m != 0) ? 1 : 0;
    for (int o = 16; o; o >>= 1) {
        sum += __shfl_down_sync(0xFFFFFFFFu, sum, o);
        sq  += __shfl_down_sync(0xFFFFFFFFu, sq, o);
        mc  += __shfl_down_sync(0xFFFFFFFFu, mc, o);
    }
    if (lane == 0) { rsum[warp] = sum; rsq[warp] = sq; rcnt[warp] = wcnt; rmask[warp] = mc; }
    __syncthreads();
    if (tid == 0) {
        float ts = 0.f, tq = 0.f; int tc = 0, tm = 0;
#pragma unroll
        for (int w = 0; w < 8; w++) {
            roff[w] = tc;
            ts += rsum[w]; tq += rsq[w]; tc += rcnt[w]; tm += rmask[w];
        }
        int cid = blockIdx.x;            // chunk id == CTA id (global)
        g_csum[cid] = ts; g_csq[cid] = tq; g_ccnt[cid] = tc; g_cmask[cid] = tm;
    }
    __syncthreads();
    if (selp) {
        int chunk = blockIdx.x & (CPB - 1);
        g_sel[fb][chunk * PPC + roff[warp] + myoff] = p & (NN - 1);
    }

    // ---------- last-CTA-per-batch finalize ----------
    __threadfence();
    __syncthreads();
    if (tid == 0) {
        int done = atomicAdd(&g_done[fb], 1);
        s_last = (done == CPB - 1) ? 1 : 0;
    }
    __syncthreads();
    if (!s_last) return;
    __threadfence();

    // warps 0-1: reduce + prefix the 64 chunk records (32 each)
    if (warp < 2) {
        int c2 = warp * 32 + lane;
        int cid = fb * CPB + c2;
        float cs = g_csum[cid], cq = g_csq[cid];
        int cc = g_ccnt[cid], cm = g_cmask[cid];
        ccnt_s[c2] = cc;
        int incl = cc;
        for (int o = 1; o < 32; o <<= 1) {
            int t = __shfl_up_sync(0xFFFFFFFFu, incl, o);
            if (lane >= o) incl += t;
        }
        cpref[c2] = incl - cc;           // prefix within this warp's 32-chunk segment
        float ts = cs, tq = cq; int tm = cm;
        for (int o = 16; o; o >>= 1) {
            ts += __shfl_down_sync(0xFFFFFFFFu, ts, o);
            tq += __shfl_down_sync(0xFFFFFFFFu, tq, o);
            tm += __shfl_down_sync(0xFFFFFFFFu, tm, o);
        }
        if (lane == 0) { swsum[warp] = ts; swsq[warp] = tq; swm[warp] = tm; }
        if (lane == 31) swtot[warp] = incl;
    }
    __syncthreads();
    if (tid == 0) {
        segoff[0] = 0; segoff[1] = swtot[0];
        f_cnt = swtot[0] + swtot[1];
        f_sum = swsum[0] + swsum[1];
        f_sq  = swsq[0] + swsq[1];
        f_nleaf = swm[0] + swm[1];
    }
    __syncthreads();

    int nleaf = f_nleaf;
    if (nleaf < 10) {
        float4 zz = make_float4(0.f, 0.f, 0.f, 0.f);
        float4* so4 = (float4*)(scores + fb * NN);
        for (int i = tid; i < NN / 4; i += TPB) so4[i] = zz;
        if (tid == 0) { conf_out[fb] = 0.0f; g_done[fb] = 0; }
        return;
    }

    // gather chunk lists into globally compacted ascending order (global scratch)
    for (int c2 = warp; c2 < CPB; c2 += 8) {
        int cc = ccnt_s[c2];
        int dst = cpref[c2] + segoff[c2 >> 5];
        for (int j = lane; j < cc; j += 32)
            g_selc[fb][dst + j] = g_sel[fb][c2 * PPC + j];
    }
    __syncthreads();                     // block-scope: our global writes visible

    const float* P = points + (size_t)fb * NN * 3;
    int cnt = f_cnt;
    int pc = cnt - 1;
    float sd = 0.0f, sd2 = 0.0f;
    for (int q = tid; q < pc; q += TPB) {
        int i1 = g_selc[fb][q], i2 = g_selc[fb][q + 1];
        float dx = P[i2 * 3 + 0] - P[i1 * 3 + 0];
        float dy = P[i2 * 3 + 1] - P[i1 * 3 + 1];
        float dz = P[i2 * 3 + 2] - P[i1 * 3 + 2];
        float d = sqrtf(dx * dx + dy * dy + dz * dz);
        sd += d; sd2 += d * d;
    }
    for (int o = 16; o; o >>= 1) {
        sd  += __shfl_down_sync(0xFFFFFFFFu, sd, o);
        sd2 += __shfl_down_sync(0xFFFFFFFFu, sd2, o);
    }
    if (lane == 0) { wsd[warp] = sd; wsd2[warp] = sd2; }
    __syncthreads();

    if (tid == 0) {
        float tsd = 0.f, tsd2 = 0.f;
#pragma unroll
        for (int w = 0; w < 8; w++) { tsd += wsd[w]; tsd2 += wsd2[w]; }
        float tsum = f_sum, tsq = f_sq;
        float nl = (float)nleaf;
        float mean = tsum / fmaxf(nl, 1.0f);
        float clarity = (tsq - 2.0f * mean * tsum + mean * mean * nl)
                        / fmaxf(nl - 1.0f, 1.0f);
        float pcf = (float)(pc > 0 ? pc : 0);
        float meand = tsd / fmaxf(pcf, 1.0f);
        float dvar = (tsd2 - 2.0f * meand * tsd + meand * meand * pcf)
                     / fmaxf(pcf - 1.0f, 1.0f);
        float cont = fminf(fmaxf(1.0f / (dvar + 1e-8f), 0.0f), 1.0f);
        cont = (cnt > 5) ? cont : 0.0f;
        float conf = fminf(fmaxf(clarity * cont, 0.0f), 1.0f);
        conf = (nleaf == 0) ? 0.0f : conf;
        conf_out[fb] = conf;
        g_done[fb] = 0;                  // restore invariant for next replay
    }
}

// ============================================================
// launch — single kernel, grid 256
// ============================================================
extern "C" void kernel_launch(void* const* d_in, const int* in_sizes, int n_in,
                              void* d_out, int out_size) {
    const float* points   = (const float*)d_in[0];
    const float* features = (const float*)d_in[1];
    const int*   mask     = (const int*)d_in[2];
    const float* W1 = (const float*)d_in[3];
    const float* b1 = (const float*)d_in[4];
    const float* W2 = (const float*)d_in[5];
    const float* b2 = (const float*)d_in[6];
    const float* W3 = (const float*)d_in[7];
    const float* b3 = (const float*)d_in[8];

    float* out_scores = (float*)d_out;                       // [B*N]
    float* out_feats  = out_scores + BB * NN;                // [B*N*F]
    float* out_conf   = out_feats + (size_t)BB * NN * FF;    // [B]

    mlp_kernel<<<(BB * NN) / PPC, TPB>>>(points, features, mask,
                                         W1, b1, W2, b2, W3, b3,
                                         out_scores, out_feats, out_conf);
}

// round 13
// speedup vs baseline: 1.2631x; 1.2631x over previous
#include <cuda_runtime.h>
#include <cuda_fp16.h>
#include <math.h>
#include <stdint.h>

#define BB 4
#define NN 8192
#define FF 64
#define H2 32
#define TPB 128           // threads per CTA = 4 warps; 1 point per thread
#define PPC 128           // points per CTA
#define CPB 64            // chunks (CTAs) per batch = 8192/128

#define XROW 88           // padded halves per X/W1 row (67 valid + bias + pad)
#define W2ROW 72          // padded halves per W2 row (64 valid)

// ---- scratch (static, no allocation) ----
__device__ float g_csum[BB * CPB];
__device__ float g_csq[BB * CPB];
__device__ int   g_ccnt[BB * CPB];
__device__ int   g_cmask[BB * CPB];
__device__ int   g_sel[BB][NN];
__device__ int   g_selc[BB][NN];
__device__ int   g_done[BB];          // zero-init; reset after each use

static __device__ __forceinline__ void mma16816(
    float& c0, float& c1, float& c2, float& c3,
    uint32_t a0, uint32_t a1, uint32_t a2, uint32_t a3,
    uint32_t b0, uint32_t b1)
{
    asm volatile(
        "mma.sync.aligned.m16n8k16.row.col.f32.f16.f16.f32 "
        "{%0,%1,%2,%3}, {%4,%5,%6,%7}, {%8,%9}, {%0,%1,%2,%3};"
        : "+f"(c0), "+f"(c1), "+f"(c2), "+f"(c3)
        : "r"(a0), "r"(a1), "r"(a2), "r"(a3), "r"(b0), "r"(b1));
}
static __device__ __forceinline__ uint32_t ldh2(const __half* p) {
    return *reinterpret_cast<const uint32_t*>(p);
}
static __device__ __forceinline__ uint32_t pack_relu(float a, float b) {
    __half2 h = __floats2half2_rn(fmaxf(a, 0.f), fmaxf(b, 0.f));
    return *reinterpret_cast<uint32_t*>(&h);
}

// ============================================================
// Single kernel: HMMA (mma.sync m16n8k16) MLP 67->64->32->1 (+mask),
// fused stats/compaction epilogue + last-CTA-per-batch finalize.
// ============================================================
__global__ __launch_bounds__(TPB) void mlp_mma_kernel(
    const float* __restrict__ points, const float* __restrict__ features,
    const int* __restrict__ mask,
    const float* __restrict__ W1, const float* __restrict__ b1,
    const float* __restrict__ W2, const float* __restrict__ b2,
    const float* __restrict__ W3, const float* __restrict__ b3,
    float* __restrict__ scores, float* __restrict__ out_feats,
    float* __restrict__ conf_out)
{
    __shared__ __align__(16) __half sX[PPC * XROW];    // 22528B (reused for h2 f32)
    __shared__ __align__(16) __half sW1[64 * XROW];    // 11264B
    __shared__ __align__(16) __half sW2[32 * W2ROW];   // 4608B
    __shared__ float sW3[H2], sb2[H2];
    __shared__ float sb3;
    __shared__ float rsum[4], rsq[4];
    __shared__ int rcnt[4], rmask[4], roff[4];
    __shared__ int cpref[CPB], ccnt_s[CPB];
    __shared__ int segoff[2];
    __shared__ float f_sum, f_sq;
    __shared__ int f_cnt, f_nleaf, s_last;
    __shared__ float wsd[4], wsd2[4];
    __shared__ float swsum[2], swsq[2];
    __shared__ int swm[2], swtot[2];

    int tid = threadIdx.x;
    int lane = tid & 31, warp = tid >> 5;
    int g = lane >> 2, c = lane & 3;       // mma fragment coords

    // ---- fill W1 smem (64 rows x 88 halves; col 67 = b1, rest pad 0) ----
    for (int idx = tid; idx < 64 * (XROW / 2); idx += TPB) {
        int j = idx / (XROW / 2), k2 = idx % (XROW / 2);
        int cc = 2 * k2;
        float a  = (cc < 67) ? W1[j * 67 + cc] : ((cc == 67) ? b1[j] : 0.f);
        float bv = (cc + 1 < 67) ? W1[j * 67 + cc + 1] : ((cc + 1 == 67) ? b1[j] : 0.f);
        *reinterpret_cast<__half2*>(&sW1[j * XROW + cc]) = __floats2half2_rn(a, bv);
    }
    // ---- fill W2 smem (32 rows x 72 halves; 64 valid) ----
    for (int idx = tid; idx < 32 * (W2ROW / 2); idx += TPB) {
        int j = idx / (W2ROW / 2), k2 = idx % (W2ROW / 2);
        int cc = 2 * k2;
        float a  = (cc < 64) ? W2[j * 64 + cc] : 0.f;
        float bv = (cc + 1 < 64) ? W2[j * 64 + cc + 1] : 0.f;
        *reinterpret_cast<__half2*>(&sW2[j * W2ROW + cc]) = __floats2half2_rn(a, bv);
    }
    if (tid < H2) { sb2[tid] = b2[tid]; sW3[tid] = W3[tid]; }
    if (tid == 0) sb3 = b3[0];

    // ---- fill X row (this thread's point) + passthrough ----
    int p = blockIdx.x * PPC + tid;
    int fb = p >> 13;
    {
        const float4* f4 = (const float4*)(features + (size_t)p * FF);
        float4* o4 = (float4*)(out_feats + (size_t)p * FF);
        __half2 xp[XROW / 2];
#pragma unroll
        for (int i = 0; i < FF / 4; i++) {
            float4 v = f4[i];
            o4[i] = v;
            xp[2 * i]     = __floats2half2_rn(v.x, v.y);
            xp[2 * i + 1] = __floats2half2_rn(v.z, v.w);
        }
        const float* pp = points + (size_t)p * 3;
        xp[32] = __floats2half2_rn(pp[0], pp[1]);
        xp[33] = __floats2half2_rn(pp[2], 1.0f);   // col 66 = z, col 67 = bias 1
#pragma unroll
        for (int i = 34; i < XROW / 2; i++) xp[i] = __floats2half2_rn(0.f, 0.f);
        uint4* dst = reinterpret_cast<uint4*>(&sX[tid * XROW]);
        const uint4* src = reinterpret_cast<const uint4*>(xp);
#pragma unroll
        for (int i = 0; i < XROW / 8; i++) dst[i] = src[i];
    }
    __syncthreads();

    // ---- layer 1: H1[32x64] = X[32x80] @ W1^T, fp32 accum ----
    float acc[2][8][4];
#pragma unroll
    for (int M = 0; M < 2; M++)
#pragma unroll
        for (int j = 0; j < 8; j++)
#pragma unroll
            for (int q = 0; q < 4; q++) acc[M][j][q] = 0.f;

    int r0 = warp * 32 + g;
#pragma unroll
    for (int t = 0; t < 5; t++) {
        int k0 = 16 * t + 2 * c;
        uint32_t a[2][4];
#pragma unroll
        for (int M = 0; M < 2; M++) {
            int rr = r0 + 16 * M;
            a[M][0] = ldh2(&sX[rr * XROW + k0]);
            a[M][1] = ldh2(&sX[(rr + 8) * XROW + k0]);
            a[M][2] = ldh2(&sX[rr * XROW + k0 + 8]);
            a[M][3] = ldh2(&sX[(rr + 8) * XROW + k0 + 8]);
        }
#pragma unroll
        for (int j = 0; j < 8; j++) {
            int n = 8 * j + g;
            uint32_t b0 = ldh2(&sW1[n * XROW + k0]);
            uint32_t b1r = ldh2(&sW1[n * XROW + k0 + 8]);
            mma16816(acc[0][j][0], acc[0][j][1], acc[0][j][2], acc[0][j][3],
                     a[0][0], a[0][1], a[0][2], a[0][3], b0, b1r);
            mma16816(acc[1][j][0], acc[1][j][1], acc[1][j][2], acc[1][j][3],
                     a[1][0], a[1][1], a[1][2], a[1][3], b0, b1r);
        }
    }

    // ---- relu + repack C-frags into layer-2 A-frags (in registers) ----
    uint32_t a2f[2][4][4];
#pragma unroll
    for (int M = 0; M < 2; M++)
#pragma unroll
        for (int t2 = 0; t2 < 4; t2++) {
            a2f[M][t2][0] = pack_relu(acc[M][2 * t2][0],     acc[M][2 * t2][1]);
            a2f[M][t2][1] = pack_relu(acc[M][2 * t2][2],     acc[M][2 * t2][3]);
            a2f[M][t2][2] = pack_relu(acc[M][2 * t2 + 1][0], acc[M][2 * t2 + 1][1]);
            a2f[M][t2][3] = pack_relu(acc[M][2 * t2 + 1][2], acc[M][2 * t2 + 1][3]);
        }

    // ---- layer 2: H2[32x32] = H1[32x64] @ W2^T ----
    float acc2[2][4][4];
#pragma unroll
    for (int M = 0; M < 2; M++)
#pragma unroll
        for (int n = 0; n < 4; n++)
#pragma unroll
            for (int q = 0; q < 4; q++) acc2[M][n][q] = 0.f;
#pragma unroll
    for (int t2 = 0; t2 < 4; t2++) {
        int k0 = 16 * t2 + 2 * c;
#pragma unroll
        for (int n = 0; n < 4; n++) {
            int nn = 8 * n + g;
            uint32_t b0 = ldh2(&sW2[nn * W2ROW + k0]);
            uint32_t b1r = ldh2(&sW2[nn * W2ROW + k0 + 8]);
            mma16816(acc2[0][n][0], acc2[0][n][1], acc2[0][n][2], acc2[0][n][3],
                     a2f[0][t2][0], a2f[0][t2][1], a2f[0][t2][2], a2f[0][t2][3], b0, b1r);
            mma16816(acc2[1][n][0], acc2[1][n][1], acc2[1][n][2], acc2[1][n][3],
                     a2f[1][t2][0], a2f[1][t2][1], a2f[1][t2][2], a2f[1][t2][3], b0, b1r);
        }
    }

    // ---- stage h2 into dead X region (warp-local rows), f32 ----
#pragma unroll
    for (int M = 0; M < 2; M++) {
        int rr = r0 + 16 * M;
        float* h0 = reinterpret_cast<float*>(&sX[rr * XROW]);
        float* h8 = reinterpret_cast<float*>(&sX[(rr + 8) * XROW]);
#pragma unroll
        for (int n = 0; n < 4; n++) {
            int col = 8 * n + 2 * c;
            h0[col] = acc2[M][n][0]; h0[col + 1] = acc2[M][n][1];
            h8[col] = acc2[M][n][2]; h8[col + 1] = acc2[M][n][3];
        }
    }
    __syncwarp();

    // ---- layer 3 (fp32): this thread's row, +b2, relu, dot W3, sigmoid ----
    float score;
    int m = mask[p];
    {
        const float* hr = reinterpret_cast<const float*>(&sX[tid * XROW]);
        float z0 = 0.f, z1 = 0.f, z2 = 0.f, z3 = 0.f;
#pragma unroll
        for (int i = 0; i < H2; i += 4) {
            z0 += sW3[i]     * fmaxf(hr[i]     + sb2[i],     0.f);
            z1 += sW3[i + 1] * fmaxf(hr[i + 1] + sb2[i + 1], 0.f);
            z2 += sW3[i + 2] * fmaxf(hr[i + 2] + sb2[i + 2], 0.f);
            z3 += sW3[i + 3] * fmaxf(hr[i + 3] + sb2[i + 3], 0.f);
        }
        float z = sb3 + (z0 + z1) + (z2 + z3);
        float sv = 1.0f / (1.0f + expf(-z));
        score = (m != 0) ? sv : 0.0f;
    }
    scores[p] = score;

    // ---------- fused stats + compaction epilogue ----------
    bool selp = (score > 0.7f);
    unsigned int bal = __ballot_sync(0xFFFFFFFFu, selp);
    int wcnt = __popc(bal);
    int myoff = __popc(bal & ((1u << lane) - 1u));

    float sum = score, sq = score * score;
    int mc = (m != 0);
    for (int o = 16; o; o >>= 1) {
        sum += __shfl_down_sync(0xFFFFFFFFu, sum, o);
        sq  += __shfl_down_sync(0xFFFFFFFFu, sq, o);
        mc  += __shfl_down_sync(0xFFFFFFFFu, mc, o);
    }
    if (lane == 0) { rsum[warp] = sum; rsq[warp] = sq; rcnt[warp] = wcnt; rmask[warp] = mc; }
    __syncthreads();
    if (tid == 0) {
        float ts = 0.f, tq = 0.f; int tc = 0, tm = 0;
#pragma unroll
        for (int w = 0; w < 4; w++) {
            roff[w] = tc;
            ts += rsum[w]; tq += rsq[w]; tc += rcnt[w]; tm += rmask[w];
        }
        int cid = blockIdx.x;
        g_csum[cid] = ts; g_csq[cid] = tq; g_ccnt[cid] = tc; g_cmask[cid] = tm;
    }
    __syncthreads();
    if (selp) {
        int chunk = blockIdx.x & (CPB - 1);
        g_sel[fb][chunk * PPC + roff[warp] + myoff] = p & (NN - 1);
    }

    // ---------- last-CTA-per-batch finalize ----------
    __threadfence();
    __syncthreads();
    if (tid == 0) {
        int done = atomicAdd(&g_done[fb], 1);
        s_last = (done == CPB - 1) ? 1 : 0;
    }
    __syncthreads();
    if (!s_last) return;
    __threadfence();

    // warps 0-1: reduce + prefix the 64 chunk records (32 each)
    if (warp < 2) {
        int c2 = warp * 32 + lane;
        int cid = fb * CPB + c2;
        float cs = g_csum[cid], cq = g_csq[cid];
        int cc = g_ccnt[cid], cm = g_cmask[cid];
        ccnt_s[c2] = cc;
        int incl = cc;
        for (int o = 1; o < 32; o <<= 1) {
            int t = __shfl_up_sync(0xFFFFFFFFu, incl, o);
            if (lane >= o) incl += t;
        }
        cpref[c2] = incl - cc;
        float ts = cs, tq = cq; int tm = cm;
        for (int o = 16; o; o >>= 1) {
            ts += __shfl_down_sync(0xFFFFFFFFu, ts, o);
            tq += __shfl_down_sync(0xFFFFFFFFu, tq, o);
            tm += __shfl_down_sync(0xFFFFFFFFu, tm, o);
        }
        if (lane == 0) { swsum[warp] = ts; swsq[warp] = tq; swm[warp] = tm; }
        if (lane == 31) swtot[warp] = incl;
    }
    __syncthreads();
    if (tid == 0) {
        segoff[0] = 0; segoff[1] = swtot[0];
        f_cnt = swtot[0] + swtot[1];
        f_sum = swsum[0] + swsum[1];
        f_sq  = swsq[0] + swsq[1];
        f_nleaf = swm[0] + swm[1];
    }
    __syncthreads();

    int nleaf = f_nleaf;
    if (nleaf < 10) {
        float4 zz = make_float4(0.f, 0.f, 0.f, 0.f);
        float4* so4 = (float4*)(scores + fb * NN);
        for (int i = tid; i < NN / 4; i += TPB) so4[i] = zz;
        if (tid == 0) { conf_out[fb] = 0.0f; g_done[fb] = 0; }
        return;
    }

    for (int c2 = warp; c2 < CPB; c2 += 4) {
        int cc = ccnt_s[c2];
        int dst = cpref[c2] + segoff[c2 >> 5];
        for (int j = lane; j < cc; j += 32)
            g_selc[fb][dst + j] = g_sel[fb][c2 * PPC + j];
    }
    __syncthreads();

    const float* P = points + (size_t)fb * NN * 3;
    int cnt = f_cnt;
    int pc = cnt - 1;
    float sd = 0.0f, sd2 = 0.0f;
    for (int q = tid; q < pc; q += TPB) {
        int i1 = g_selc[fb][q], i2 = g_selc[fb][q + 1];
        float dx = P[i2 * 3 + 0] - P[i1 * 3 + 0];
        float dy = P[i2 * 3 + 1] - P[i1 * 3 + 1];
        float dz = P[i2 * 3 + 2] - P[i1 * 3 + 2];
        float d = sqrtf(dx * dx + dy * dy + dz * dz);
        sd += d; sd2 += d * d;
    }
    for (int o = 16; o; o >>= 1) {
        sd  += __shfl_down_sync(0xFFFFFFFFu, sd, o);
        sd2 += __shfl_down_sync(0xFFFFFFFFu, sd2, o);
    }
    if (lane == 0) { wsd[warp] = sd; wsd2[warp] = sd2; }
    __syncthreads();

    if (tid == 0) {
        float tsd = 0.f, tsd2 = 0.f;
#pragma unroll
        for (int w = 0; w < 4; w++) { tsd += wsd[w]; tsd2 += wsd2[w]; }
        float tsum = f_sum, tsq = f_sq;
        float nl = (float)nleaf;
        float mean = tsum / fmaxf(nl, 1.0f);
        float clarity = (tsq - 2.0f * mean * tsum + mean * mean * nl)
                        / fmaxf(nl - 1.0f, 1.0f);
        float pcf = (float)(pc > 0 ? pc : 0);
        float meand = tsd / fmaxf(pcf, 1.0f);
        float dvar = (tsd2 - 2.0f * meand * tsd + meand * meand * pcf)
                     / fmaxf(pcf - 1.0f, 1.0f);
        float cont = fminf(fmaxf(1.0f / (dvar + 1e-8f), 0.0f), 1.0f);
        cont = (cnt > 5) ? cont : 0.0f;
        float conf = fminf(fmaxf(clarity * cont, 0.0f), 1.0f);
        conf = (nleaf == 0) ? 0.0f : conf;
        conf_out[fb] = conf;
        g_done[fb] = 0;
    }
}

// ============================================================
// launch — single kernel, grid 256
// ============================================================
extern "C" void kernel_launch(void* const* d_in, const int* in_sizes, int n_in,
                              void* d_out, int out_size) {
    const float* points   = (const float*)d_in[0];
    const float* features = (const float*)d_in[1];
    const int*   mask     = (const int*)d_in[2];
    const float* W1 = (const float*)d_in[3];
    const float* b1 = (const float*)d_in[4];
    const float* W2 = (const float*)d_in[5];
    const float* b2 = (const float*)d_in[6];
    const float* W3 = (const float*)d_in[7];
    const float* b3 = (const float*)d_in[8];

    float* out_scores = (float*)d_out;                       // [B*N]
    float* out_feats  = out_scores + BB * NN;                // [B*N*F]
    float* out_conf   = out_feats + (size_t)BB * NN * FF;    // [B]

    mlp_mma_kernel<<<(BB * NN) / PPC, TPB>>>(
        points, features, mask, W1, b1, W2, b2, W3, b3,
        out_scores, out_feats, out_conf);
}

// round 14
// speedup vs baseline: 1.5729x; 1.2453x over previous
#include <cuda_runtime.h>
#include <cuda_fp16.h>
#include <math.h>
#include <stdint.h>

#define BB 4
#define NN 8192
#define FF 64
#define H2 32
#define TPB 128           // threads per CTA = 4 warps; 1 point per thread
#define PPC 128           // points per CTA
#define CPB 64            // chunks (CTAs) per batch = 8192/128

#define XROW 88           // padded halves per X/W1 row (67 valid + bias + pad)
#define W2ROW 72          // padded halves per W2 row (64 valid)

// ---- scratch (static, no allocation) ----
__device__ float g_csum[BB * CPB];
__device__ float g_csq[BB * CPB];
__device__ int   g_ccnt[BB * CPB];
__device__ int   g_cmask[BB * CPB];
__device__ int   g_sel[BB][NN];
__device__ int   g_selc[BB][NN];
__device__ int   g_done[BB];          // zero-init; reset after each use

static __device__ __forceinline__ void mma16816(
    float& c0, float& c1, float& c2, float& c3,
    uint32_t a0, uint32_t a1, uint32_t a2, uint32_t a3,
    uint32_t b0, uint32_t b1)
{
    asm volatile(
        "mma.sync.aligned.m16n8k16.row.col.f32.f16.f16.f32 "
        "{%0,%1,%2,%3}, {%4,%5,%6,%7}, {%8,%9}, {%0,%1,%2,%3};"
        : "+f"(c0), "+f"(c1), "+f"(c2), "+f"(c3)
        : "r"(a0), "r"(a1), "r"(a2), "r"(a3), "r"(b0), "r"(b1));
}
static __device__ __forceinline__ uint32_t ldh2(const __half* p) {
    return *reinterpret_cast<const uint32_t*>(p);
}
static __device__ __forceinline__ uint32_t pack_relu(float a, float b) {
    __half2 h = __floats2half2_rn(fmaxf(a, 0.f), fmaxf(b, 0.f));
    return *reinterpret_cast<uint32_t*>(&h);
}

// ============================================================
// Single kernel: HMMA (mma.sync m16n8k16) MLP 67->64->32->1 (+mask),
// COALESCED feature streaming, fused stats/compaction epilogue +
// last-CTA-per-batch finalize.
// ============================================================
__global__ __launch_bounds__(TPB) void mlp_mma_kernel(
    const float* __restrict__ points, const float* __restrict__ features,
    const int* __restrict__ mask,
    const float* __restrict__ W1, const float* __restrict__ b1,
    const float* __restrict__ W2, const float* __restrict__ b2,
    const float* __restrict__ W3, const float* __restrict__ b3,
    float* __restrict__ scores, float* __restrict__ out_feats,
    float* __restrict__ conf_out)
{
    __shared__ __align__(16) __half sX[PPC * XROW];    // 22528B (reused for h2 f32)
    __shared__ __align__(16) __half sW1[64 * XROW];    // 11264B
    __shared__ __align__(16) __half sW2[32 * W2ROW];   // 4608B
    __shared__ float sW3[H2], sb2[H2];
    __shared__ float sb3;
    __shared__ float rsum[4], rsq[4];
    __shared__ int rcnt[4], rmask[4], roff[4];
    __shared__ int cpref[CPB], ccnt_s[CPB];
    __shared__ int segoff[2];
    __shared__ float f_sum, f_sq;
    __shared__ int f_cnt, f_nleaf, s_last;
    __shared__ float wsd[4], wsd2[4];
    __shared__ float swsum[2], swsq[2];
    __shared__ int swm[2], swtot[2];

    int tid = threadIdx.x;
    int lane = tid & 31, warp = tid >> 5;
    int g = lane >> 2, c = lane & 3;       // mma fragment coords

    int p = blockIdx.x * PPC + tid;
    int fb = p >> 13;

    // early latency-critical per-point loads (overlap with prologue)
    const float* pp = points + (size_t)p * 3;
    float px = pp[0], py = pp[1], pz = pp[2];
    int m = mask[p];

    // ---- COALESCED feature stream: copy + convert ----
    // CTA covers 128 points x 16 float4 = 2048 float4, fully coalesced.
    {
        int pbase = blockIdx.x * PPC;
        const float4* f4 = (const float4*)(features + (size_t)pbase * FF);
        float4* o4 = (float4*)(out_feats + (size_t)pbase * FF);
#pragma unroll
        for (int k = 0; k < 16; k++) {
            int j = tid + k * TPB;
            float4 v = f4[j];
            o4[j] = v;
            int row = j >> 4, col4 = j & 15;
            __half2* dst = reinterpret_cast<__half2*>(&sX[row * XROW + col4 * 4]);
            dst[0] = __floats2half2_rn(v.x, v.y);
            dst[1] = __floats2half2_rn(v.z, v.w);
        }
    }

    // ---- fill W1 smem (64 rows x 88 halves; col 67 = b1, rest pad 0) ----
    for (int idx = tid; idx < 64 * (XROW / 2); idx += TPB) {
        int j = idx / (XROW / 2), k2 = idx % (XROW / 2);
        int cc = 2 * k2;
        float a  = (cc < 67) ? W1[j * 67 + cc] : ((cc == 67) ? b1[j] : 0.f);
        float bv = (cc + 1 < 67) ? W1[j * 67 + cc + 1] : ((cc + 1 == 67) ? b1[j] : 0.f);
        *reinterpret_cast<__half2*>(&sW1[j * XROW + cc]) = __floats2half2_rn(a, bv);
    }
    // ---- fill W2 smem (32 rows x 72 halves; 64 valid) ----
    for (int idx = tid; idx < 32 * (W2ROW / 2); idx += TPB) {
        int j = idx / (W2ROW / 2), k2 = idx % (W2ROW / 2);
        int cc = 2 * k2;
        float a  = (cc < 64) ? W2[j * 64 + cc] : 0.f;
        float bv = (cc + 1 < 64) ? W2[j * 64 + cc + 1] : 0.f;
        *reinterpret_cast<__half2*>(&sW2[j * W2ROW + cc]) = __floats2half2_rn(a, bv);
    }
    if (tid < H2) { sb2[tid] = b2[tid]; sW3[tid] = W3[tid]; }
    if (tid == 0) sb3 = b3[0];

    // ---- X tail columns 64..87 for own row: xyz, bias=1, pad 0 ----
    {
        __half2* xr = reinterpret_cast<__half2*>(&sX[tid * XROW + 64]);
        xr[0] = __floats2half2_rn(px, py);
        xr[1] = __floats2half2_rn(pz, 1.0f);     // col 66 = z, col 67 = bias
#pragma unroll
        for (int i = 2; i < 12; i++) xr[i] = __floats2half2_rn(0.f, 0.f);
    }
    __syncthreads();

    // ---- layer 1: H1[32x64] = X[32x80] @ W1^T, fp32 accum ----
    float acc[2][8][4];
#pragma unroll
    for (int M = 0; M < 2; M++)
#pragma unroll
        for (int j = 0; j < 8; j++)
#pragma unroll
            for (int q = 0; q < 4; q++) acc[M][j][q] = 0.f;

    int r0 = warp * 32 + g;
#pragma unroll
    for (int t = 0; t < 5; t++) {
        int k0 = 16 * t + 2 * c;
        uint32_t a[2][4];
#pragma unroll
        for (int M = 0; M < 2; M++) {
            int rr = r0 + 16 * M;
            a[M][0] = ldh2(&sX[rr * XROW + k0]);
            a[M][1] = ldh2(&sX[(rr + 8) * XROW + k0]);
            a[M][2] = ldh2(&sX[rr * XROW + k0 + 8]);
            a[M][3] = ldh2(&sX[(rr + 8) * XROW + k0 + 8]);
        }
#pragma unroll
        for (int j = 0; j < 8; j++) {
            int n = 8 * j + g;
            uint32_t b0 = ldh2(&sW1[n * XROW + k0]);
            uint32_t b1r = ldh2(&sW1[n * XROW + k0 + 8]);
            mma16816(acc[0][j][0], acc[0][j][1], acc[0][j][2], acc[0][j][3],
                     a[0][0], a[0][1], a[0][2], a[0][3], b0, b1r);
            mma16816(acc[1][j][0], acc[1][j][1], acc[1][j][2], acc[1][j][3],
                     a[1][0], a[1][1], a[1][2], a[1][3], b0, b1r);
        }
    }

    // ---- relu + repack C-frags into layer-2 A-frags (in registers) ----
    uint32_t a2f[2][4][4];
#pragma unroll
    for (int M = 0; M < 2; M++)
#pragma unroll
        for (int t2 = 0; t2 < 4; t2++) {
            a2f[M][t2][0] = pack_relu(acc[M][2 * t2][0],     acc[M][2 * t2][1]);
            a2f[M][t2][1] = pack_relu(acc[M][2 * t2][2],     acc[M][2 * t2][3]);
            a2f[M][t2][2] = pack_relu(acc[M][2 * t2 + 1][0], acc[M][2 * t2 + 1][1]);
            a2f[M][t2][3] = pack_relu(acc[M][2 * t2 + 1][2], acc[M][2 * t2 + 1][3]);
        }

    // ---- layer 2: H2[32x32] = H1[32x64] @ W2^T ----
    float acc2[2][4][4];
#pragma unroll
    for (int M = 0; M < 2; M++)
#pragma unroll
        for (int n = 0; n < 4; n++)
#pragma unroll
            for (int q = 0; q < 4; q++) acc2[M][n][q] = 0.f;
#pragma unroll
    for (int t2 = 0; t2 < 4; t2++) {
        int k0 = 16 * t2 + 2 * c;
#pragma unroll
        for (int n = 0; n < 4; n++) {
            int nn = 8 * n + g;
            uint32_t b0 = ldh2(&sW2[nn * W2ROW + k0]);
            uint32_t b1r = ldh2(&sW2[nn * W2ROW + k0 + 8]);
            mma16816(acc2[0][n][0], acc2[0][n][1], acc2[0][n][2], acc2[0][n][3],
                     a2f[0][t2][0], a2f[0][t2][1], a2f[0][t2][2], a2f[0][t2][3], b0, b1r);
            mma16816(acc2[1][n][0], acc2[1][n][1], acc2[1][n][2], acc2[1][n][3],
                     a2f[1][t2][0], a2f[1][t2][1], a2f[1][t2][2], a2f[1][t2][3], b0, b1r);
        }
    }

    // ---- stage h2 into dead X region (warp-local rows), f32 ----
#pragma unroll
    for (int M = 0; M < 2; M++) {
        int rr = r0 + 16 * M;
        float* h0 = reinterpret_cast<float*>(&sX[rr * XROW]);
        float* h8 = reinterpret_cast<float*>(&sX[(rr + 8) * XROW]);
#pragma unroll
        for (int n = 0; n < 4; n++) {
            int col = 8 * n + 2 * c;
            h0[col] = acc2[M][n][0]; h0[col + 1] = acc2[M][n][1];
            h8[col] = acc2[M][n][2]; h8[col + 1] = acc2[M][n][3];
        }
    }
    __syncwarp();

    // ---- layer 3 (fp32): this thread's row, +b2, relu, dot W3, sigmoid ----
    float score;
    {
        const float* hr = reinterpret_cast<const float*>(&sX[tid * XROW]);
        float z0 = 0.f, z1 = 0.f, z2 = 0.f, z3 = 0.f;
#pragma unroll
        for (int i = 0; i < H2; i += 4) {
            z0 += sW3[i]     * fmaxf(hr[i]     + sb2[i],     0.f);
            z1 += sW3[i + 1] * fmaxf(hr[i + 1] + sb2[i + 1], 0.f);
            z2 += sW3[i + 2] * fmaxf(hr[i + 2] + sb2[i + 2], 0.f);
            z3 += sW3[i + 3] * fmaxf(hr[i + 3] + sb2[i + 3], 0.f);
        }
        float z = sb3 + (z0 + z1) + (z2 + z3);
        float sv = 1.0f / (1.0f + expf(-z));
        score = (m != 0) ? sv : 0.0f;
    }
    scores[p] = score;

    // ---------- fused stats + compaction epilogue ----------
    bool selp = (score > 0.7f);
    unsigned int bal = __ballot_sync(0xFFFFFFFFu, selp);
    int wcnt = __popc(bal);
    int myoff = __popc(bal & ((1u << lane) - 1u));

    float sum = score, sq = score * score;
    int mc = (m != 0);
    for (int o = 16; o; o >>= 1) {
        sum += __shfl_down_sync(0xFFFFFFFFu, sum, o);
        sq  += __shfl_down_sync(0xFFFFFFFFu, sq, o);
        mc  += __shfl_down_sync(0xFFFFFFFFu, mc, o);
    }
    if (lane == 0) { rsum[warp] = sum; rsq[warp] = sq; rcnt[warp] = wcnt; rmask[warp] = mc; }
    __syncthreads();
    if (tid == 0) {
        float ts = 0.f, tq = 0.f; int tc = 0, tm = 0;
#pragma unroll
        for (int w = 0; w < 4; w++) {
            roff[w] = tc;
            ts += rsum[w]; tq += rsq[w]; tc += rcnt[w]; tm += rmask[w];
        }
        int cid = blockIdx.x;
        g_csum[cid] = ts; g_csq[cid] = tq; g_ccnt[cid] = tc; g_cmask[cid] = tm;
    }
    __syncthreads();
    if (selp) {
        int chunk = blockIdx.x & (CPB - 1);
        g_sel[fb][chunk * PPC + roff[warp] + myoff] = p & (NN - 1);
    }

    // ---------- last-CTA-per-batch finalize ----------
    __threadfence();
    __syncthreads();
    if (tid == 0) {
        int done = atomicAdd(&g_done[fb], 1);
        s_last = (done == CPB - 1) ? 1 : 0;
    }
    __syncthreads();
    if (!s_last) return;
    __threadfence();

    // warps 0-1: reduce + prefix the 64 chunk records (32 each)
    if (warp < 2) {
        int c2 = warp * 32 + lane;
        int cid = fb * CPB + c2;
        float cs = g_csum[cid], cq = g_csq[cid];
        int cc = g_ccnt[cid], cm = g_cmask[cid];
        ccnt_s[c2] = cc;
        int incl = cc;
        for (int o = 1; o < 32; o <<= 1) {
            int t = __shfl_up_sync(0xFFFFFFFFu, incl, o);
            if (lane >= o) incl += t;
        }
        cpref[c2] = incl - cc;
        float ts = cs, tq = cq; int tm = cm;
        for (int o = 16; o; o >>= 1) {
            ts += __shfl_down_sync(0xFFFFFFFFu, ts, o);
            tq += __shfl_down_sync(0xFFFFFFFFu, tq, o);
            tm += __shfl_down_sync(0xFFFFFFFFu, tm, o);
        }
        if (lane == 0) { swsum[warp] = ts; swsq[warp] = tq; swm[warp] = tm; }
        if (lane == 31) swtot[warp] = incl;
    }
    __syncthreads();
    if (tid == 0) {
        segoff[0] = 0; segoff[1] = swtot[0];
        f_cnt = swtot[0] + swtot[1];
        f_sum = swsum[0] + swsum[1];
        f_sq  = swsq[0] + swsq[1];
        f_nleaf = swm[0] + swm[1];
    }
    __syncthreads();

    int nleaf = f_nleaf;
    if (nleaf < 10) {
        float4 zz = make_float4(0.f, 0.f, 0.f, 0.f);
        float4* so4 = (float4*)(scores + fb * NN);
        for (int i = tid; i < NN / 4; i += TPB) so4[i] = zz;
        if (tid == 0) { conf_out[fb] = 0.0f; g_done[fb] = 0; }
        return;
    }

    for (int c2 = warp; c2 < CPB; c2 += 4) {
        int cc = ccnt_s[c2];
        int dst = cpref[c2] + segoff[c2 >> 5];
        for (int j = lane; j < cc; j += 32)
            g_selc[fb][dst + j] = g_sel[fb][c2 * PPC + j];
    }
    __syncthreads();

    const float* P = points + (size_t)fb * NN * 3;
    int cnt = f_cnt;
    int pc = cnt - 1;
    float sd = 0.0f, sd2 = 0.0f;
    for (int q = tid; q < pc; q += TPB) {
        int i1 = g_selc[fb][q], i2 = g_selc[fb][q + 1];
        float dx = P[i2 * 3 + 0] - P[i1 * 3 + 0];
        float dy = P[i2 * 3 + 1] - P[i1 * 3 + 1];
        float dz = P[i2 * 3 + 2] - P[i1 * 3 + 2];
        float d = sqrtf(dx * dx + dy * dy + dz * dz);
        sd += d; sd2 += d * d;
    }
    for (int o = 16; o; o >>= 1) {
        sd  += __shfl_down_sync(0xFFFFFFFFu, sd, o);
        sd2 += __shfl_down_sync(0xFFFFFFFFu, sd2, o);
    }
    if (lane == 0) { wsd[warp] = sd; wsd2[warp] = sd2; }
    __syncthreads();

    if (tid == 0) {
        float tsd = 0.f, tsd2 = 0.f;
#pragma unroll
        for (int w = 0; w < 4; w++) { tsd += wsd[w]; tsd2 += wsd2[w]; }
        float tsum = f_sum, tsq = f_sq;
        float nl = (float)nleaf;
        float mean = tsum / fmaxf(nl, 1.0f);
        float clarity = (tsq - 2.0f * mean * tsum + mean * mean * nl)
                        / fmaxf(nl - 1.0f, 1.0f);
        float pcf = (float)(pc > 0 ? pc : 0);
        float meand = tsd / fmaxf(pcf, 1.0f);
        float dvar = (tsd2 - 2.0f * meand * tsd + meand * meand * pcf)
                     / fmaxf(pcf - 1.0f, 1.0f);
        float cont = fminf(fmaxf(1.0f / (dvar + 1e-8f), 0.0f), 1.0f);
        cont = (cnt > 5) ? cont : 0.0f;
        float conf = fminf(fmaxf(clarity * cont, 0.0f), 1.0f);
        conf = (nleaf == 0) ? 0.0f : conf;
        conf_out[fb] = conf;
        g_done[fb] = 0;
    }
}

// ============================================================
// launch — single kernel, grid 256
// ============================================================
extern "C" void kernel_launch(void* const* d_in, const int* in_sizes, int n_in,
                              void* d_out, int out_size) {
    const float* points   = (const float*)d_in[0];
    const float* features = (const float*)d_in[1];
    const int*   mask     = (const int*)d_in[2];
    const float* W1 = (const float*)d_in[3];
    const float* b1 = (const float*)d_in[4];
    const float* W2 = (const float*)d_in[5];
    const float* b2 = (const float*)d_in[6];
    const float* W3 = (const float*)d_in[7];
    const float* b3 = (const float*)d_in[8];

    float* out_scores = (float*)d_out;                       // [B*N]
    float* out_feats  = out_scores + BB * NN;                // [B*N*F]
    float* out_conf   = out_feats + (size_t)BB * NN * FF;    // [B]

    mlp_mma_kernel<<<(BB * NN) / PPC, TPB>>>(
        points, features, mask, W1, b1, W2, b2, W3, b3,
        out_scores, out_feats, out_conf);
}

// round 15
// speedup vs baseline: 1.8753x; 1.1922x over previous
#include <cuda_runtime.h>
#include <cuda_fp16.h>
#include <math.h>
#include <stdint.h>

#define BB 4
#define NN 8192
#define FF 64
#define H2 32
#define TPB 256           // threads per CTA = 8 warps; 1 point per thread
#define PPC 256           // points per CTA
#define CPB 32            // chunks (CTAs) per batch = 8192/256

#define XROW 88           // padded halves per X/W1 row (67 valid + bias + pad)
#define W2ROW 72          // padded halves per W2 row (64 valid)

// dynamic smem carve
#define SX_BYTES  (PPC * XROW * 2)          // 45056
#define SW1_OFF   SX_BYTES                  // 45056
#define SW2_OFF   (SW1_OFF + 64 * XROW * 2) // 56320
#define DYN_BYTES (SW2_OFF + 32 * W2ROW * 2)// 60928

// ---- scratch (static, no allocation) ----
__device__ float g_csum[BB * CPB];
__device__ float g_csq[BB * CPB];
__device__ int   g_ccnt[BB * CPB];
__device__ int   g_cmask[BB * CPB];
__device__ int   g_sel[BB][NN];
__device__ int   g_selc[BB][NN];
__device__ int   g_done[BB];          // zero-init; reset after each use

static __device__ __forceinline__ void mma16816(
    float& c0, float& c1, float& c2, float& c3,
    uint32_t a0, uint32_t a1, uint32_t a2, uint32_t a3,
    uint32_t b0, uint32_t b1)
{
    asm volatile(
        "mma.sync.aligned.m16n8k16.row.col.f32.f16.f16.f32 "
        "{%0,%1,%2,%3}, {%4,%5,%6,%7}, {%8,%9}, {%0,%1,%2,%3};"
        : "+f"(c0), "+f"(c1), "+f"(c2), "+f"(c3)
        : "r"(a0), "r"(a1), "r"(a2), "r"(a3), "r"(b0), "r"(b1));
}
static __device__ __forceinline__ uint32_t ldh2(const __half* p) {
    return *reinterpret_cast<const uint32_t*>(p);
}
static __device__ __forceinline__ uint32_t pack_relu(float a, float b) {
    __half2 h = __floats2half2_rn(fmaxf(a, 0.f), fmaxf(b, 0.f));
    return *reinterpret_cast<uint32_t*>(&h);
}

extern __shared__ __align__(16) char dynsmem[];

// ============================================================
// Single kernel: HMMA MLP 67->64->32->1 (+mask), coalesced streaming,
// fused stats/compaction epilogue + last-CTA-per-batch finalize.
// 256 pts/CTA -> grid 128 -> SINGLE WAVE on 148 SMs.
// ============================================================
__global__ __launch_bounds__(TPB) void mlp_mma_kernel(
    const float* __restrict__ points, const float* __restrict__ features,
    const int* __restrict__ mask,
    const float* __restrict__ W1, const float* __restrict__ b1,
    const float* __restrict__ W2, const float* __restrict__ b2,
    const float* __restrict__ W3, const float* __restrict__ b3,
    float* __restrict__ scores, float* __restrict__ out_feats,
    float* __restrict__ conf_out)
{
    __half* sX  = reinterpret_cast<__half*>(dynsmem);
    __half* sW1 = reinterpret_cast<__half*>(dynsmem + SW1_OFF);
    __half* sW2 = reinterpret_cast<__half*>(dynsmem + SW2_OFF);

    __shared__ float sW3[H2], sb2[H2];
    __shared__ float sb3;
    __shared__ float rsum[8], rsq[8];
    __shared__ int rcnt[8], rmask[8], roff[8];
    __shared__ int cpref[CPB], ccnt_s[CPB];
    __shared__ float f_sum, f_sq;
    __shared__ int f_cnt, f_nleaf, s_last;
    __shared__ float wsd[8], wsd2[8];

    int tid = threadIdx.x;
    int lane = tid & 31, warp = tid >> 5;
    int g = lane >> 2, c = lane & 3;       // mma fragment coords

    int p = blockIdx.x * PPC + tid;
    int fb = p >> 13;

    // early latency-critical per-point loads (overlap with prologue)
    const float* pp = points + (size_t)p * 3;
    float px = pp[0], py = pp[1], pz = pp[2];
    int m = mask[p];

    // ---- COALESCED feature stream: copy + convert ----
    // CTA covers 256 points x 16 float4 = 4096 float4, fully coalesced.
    {
        int pbase = blockIdx.x * PPC;
        const float4* f4 = (const float4*)(features + (size_t)pbase * FF);
        float4* o4 = (float4*)(out_feats + (size_t)pbase * FF);
#pragma unroll
        for (int k = 0; k < 16; k++) {
            int j = tid + k * TPB;
            float4 v = f4[j];
            o4[j] = v;
            int row = j >> 4, col4 = j & 15;
            __half2* dst = reinterpret_cast<__half2*>(&sX[row * XROW + col4 * 4]);
            dst[0] = __floats2half2_rn(v.x, v.y);
            dst[1] = __floats2half2_rn(v.z, v.w);
        }
    }

    // ---- fill W1 smem (64 rows x 88 halves; col 67 = b1, rest pad 0) ----
    for (int idx = tid; idx < 64 * (XROW / 2); idx += TPB) {
        int j = idx / (XROW / 2), k2 = idx % (XROW / 2);
        int cc = 2 * k2;
        float a  = (cc < 67) ? W1[j * 67 + cc] : ((cc == 67) ? b1[j] : 0.f);
        float bv = (cc + 1 < 67) ? W1[j * 67 + cc + 1] : ((cc + 1 == 67) ? b1[j] : 0.f);
        *reinterpret_cast<__half2*>(&sW1[j * XROW + cc]) = __floats2half2_rn(a, bv);
    }
    // ---- fill W2 smem (32 rows x 72 halves; 64 valid) ----
    for (int idx = tid; idx < 32 * (W2ROW / 2); idx += TPB) {
        int j = idx / (W2ROW / 2), k2 = idx % (W2ROW / 2);
        int cc = 2 * k2;
        float a  = (cc < 64) ? W2[j * 64 + cc] : 0.f;
        float bv = (cc + 1 < 64) ? W2[j * 64 + cc + 1] : 0.f;
        *reinterpret_cast<__half2*>(&sW2[j * W2ROW + cc]) = __floats2half2_rn(a, bv);
    }
    if (tid < H2) { sb2[tid] = b2[tid]; sW3[tid] = W3[tid]; }
    if (tid == 0) sb3 = b3[0];

    // ---- X tail columns 64..87 for own row: xyz, bias=1, pad 0 ----
    {
        __half2* xr = reinterpret_cast<__half2*>(&sX[tid * XROW + 64]);
        xr[0] = __floats2half2_rn(px, py);
        xr[1] = __floats2half2_rn(pz, 1.0f);     // col 66 = z, col 67 = bias
#pragma unroll
        for (int i = 2; i < 12; i++) xr[i] = __floats2half2_rn(0.f, 0.f);
    }
    __syncthreads();

    // ---- layer 1: per-warp H1[32x64] = X[32x80] @ W1^T, fp32 accum ----
    float acc[2][8][4];
#pragma unroll
    for (int M = 0; M < 2; M++)
#pragma unroll
        for (int j = 0; j < 8; j++)
#pragma unroll
            for (int q = 0; q < 4; q++) acc[M][j][q] = 0.f;

    int r0 = warp * 32 + g;
#pragma unroll
    for (int t = 0; t < 5; t++) {
        int k0 = 16 * t + 2 * c;
        uint32_t a[2][4];
#pragma unroll
        for (int M = 0; M < 2; M++) {
            int rr = r0 + 16 * M;
            a[M][0] = ldh2(&sX[rr * XROW + k0]);
            a[M][1] = ldh2(&sX[(rr + 8) * XROW + k0]);
            a[M][2] = ldh2(&sX[rr * XROW + k0 + 8]);
            a[M][3] = ldh2(&sX[(rr + 8) * XROW + k0 + 8]);
        }
#pragma unroll
        for (int j = 0; j < 8; j++) {
            int n = 8 * j + g;
            uint32_t b0 = ldh2(&sW1[n * XROW + k0]);
            uint32_t b1r = ldh2(&sW1[n * XROW + k0 + 8]);
            mma16816(acc[0][j][0], acc[0][j][1], acc[0][j][2], acc[0][j][3],
                     a[0][0], a[0][1], a[0][2], a[0][3], b0, b1r);
            mma16816(acc[1][j][0], acc[1][j][1], acc[1][j][2], acc[1][j][3],
                     a[1][0], a[1][1], a[1][2], a[1][3], b0, b1r);
        }
    }

    // ---- relu + repack C-frags into layer-2 A-frags (in registers) ----
    uint32_t a2f[2][4][4];
#pragma unroll
    for (int M = 0; M < 2; M++)
#pragma unroll
        for (int t2 = 0; t2 < 4; t2++) {
            a2f[M][t2][0] = pack_relu(acc[M][2 * t2][0],     acc[M][2 * t2][1]);
            a2f[M][t2][1] = pack_relu(acc[M][2 * t2][2],     acc[M][2 * t2][3]);
            a2f[M][t2][2] = pack_relu(acc[M][2 * t2 + 1][0], acc[M][2 * t2 + 1][1]);
            a2f[M][t2][3] = pack_relu(acc[M][2 * t2 + 1][2], acc[M][2 * t2 + 1][3]);
        }

    // ---- layer 2: H2[32x32] = H1[32x64] @ W2^T ----
    float acc2[2][4][4];
#pragma unroll
    for (int M = 0; M < 2; M++)
#pragma unroll
        for (int n = 0; n < 4; n++)
#pragma unroll
            for (int q = 0; q < 4; q++) acc2[M][n][q] = 0.f;
#pragma unroll
    for (int t2 = 0; t2 < 4; t2++) {
        int k0 = 16 * t2 + 2 * c;
#pragma unroll
        for (int n = 0; n < 4; n++) {
            int nn = 8 * n + g;
            uint32_t b0 = ldh2(&sW2[nn * W2ROW + k0]);
            uint32_t b1r = ldh2(&sW2[nn * W2ROW + k0 + 8]);
            mma16816(acc2[0][n][0], acc2[0][n][1], acc2[0][n][2], acc2[0][n][3],
                     a2f[0][t2][0], a2f[0][t2][1], a2f[0][t2][2], a2f[0][t2][3], b0, b1r);
            mma16816(acc2[1][n][0], acc2[1][n][1], acc2[1][n][2], acc2[1][n][3],
                     a2f[1][t2][0], a2f[1][t2][1], a2f[1][t2][2], a2f[1][t2][3], b0, b1r);
        }
    }

    // ---- stage h2 into dead X region (warp-local rows), f32 ----
#pragma unroll
    for (int M = 0; M < 2; M++) {
        int rr = r0 + 16 * M;
        float* h0 = reinterpret_cast<float*>(&sX[rr * XROW]);
        float* h8 = reinterpret_cast<float*>(&sX[(rr + 8) * XROW]);
#pragma unroll
        for (int n = 0; n < 4; n++) {
            int col = 8 * n + 2 * c;
            h0[col] = acc2[M][n][0]; h0[col + 1] = acc2[M][n][1];
            h8[col] = acc2[M][n][2]; h8[col + 1] = acc2[M][n][3];
        }
    }
    __syncwarp();

    // ---- layer 3 (fp32): this thread's row, +b2, relu, dot W3, sigmoid ----
    float score;
    {
        const float* hr = reinterpret_cast<const float*>(&sX[tid * XROW]);
        float z0 = 0.f, z1 = 0.f, z2 = 0.f, z3 = 0.f;
#pragma unroll
        for (int i = 0; i < H2; i += 4) {
            z0 += sW3[i]     * fmaxf(hr[i]     + sb2[i],     0.f);
            z1 += sW3[i + 1] * fmaxf(hr[i + 1] + sb2[i + 1], 0.f);
            z2 += sW3[i + 2] * fmaxf(hr[i + 2] + sb2[i + 2], 0.f);
            z3 += sW3[i + 3] * fmaxf(hr[i + 3] + sb2[i + 3], 0.f);
        }
        float z = sb3 + (z0 + z1) + (z2 + z3);
        float sv = 1.0f / (1.0f + expf(-z));
        score = (m != 0) ? sv : 0.0f;
    }
    scores[p] = score;

    // ---------- fused stats + compaction epilogue ----------
    bool selp = (score > 0.7f);
    unsigned int bal = __ballot_sync(0xFFFFFFFFu, selp);
    int wcnt = __popc(bal);
    int myoff = __popc(bal & ((1u << lane) - 1u));

    float sum = score, sq = score * score;
    int mc = (m != 0);
    for (int o = 16; o; o >>= 1) {
        sum += __shfl_down_sync(0xFFFFFFFFu, sum, o);
        sq  += __shfl_down_sync(0xFFFFFFFFu, sq, o);
        mc  += __shfl_down_sync(0xFFFFFFFFu, mc, o);
    }
    if (lane == 0) { rsum[warp] = sum; rsq[warp] = sq; rcnt[warp] = wcnt; rmask[warp] = mc; }
    __syncthreads();
    if (tid == 0) {
        float ts = 0.f, tq = 0.f; int tc = 0, tm = 0;
#pragma unroll
        for (int w = 0; w < 8; w++) {
            roff[w] = tc;
            ts += rsum[w]; tq += rsq[w]; tc += rcnt[w]; tm += rmask[w];
        }
        int cid = blockIdx.x;
        g_csum[cid] = ts; g_csq[cid] = tq; g_ccnt[cid] = tc; g_cmask[cid] = tm;
    }
    __syncthreads();
    if (selp) {
        int chunk = blockIdx.x & (CPB - 1);
        g_sel[fb][chunk * PPC + roff[warp] + myoff] = p & (NN - 1);
    }

    // ---------- last-CTA-per-batch finalize ----------
    __threadfence();
    __syncthreads();
    if (tid == 0) {
        int done = atomicAdd(&g_done[fb], 1);
        s_last = (done == CPB - 1) ? 1 : 0;
    }
    __syncthreads();
    if (!s_last) return;
    __threadfence();

    // warp 0: reduce + prefix the 32 chunk records of batch fb
    if (warp == 0) {
        int cid = fb * CPB + lane;
        float cs = g_csum[cid], cq = g_csq[cid];
        int cc = g_ccnt[cid], cm = g_cmask[cid];
        ccnt_s[lane] = cc;
        int incl = cc;
        for (int o = 1; o < 32; o <<= 1) {
            int t = __shfl_up_sync(0xFFFFFFFFu, incl, o);
            if (lane >= o) incl += t;
        }
        cpref[lane] = incl - cc;
        float ts = cs, tq = cq; int tm = cm;
        for (int o = 16; o; o >>= 1) {
            ts += __shfl_down_sync(0xFFFFFFFFu, ts, o);
            tq += __shfl_down_sync(0xFFFFFFFFu, tq, o);
            tm += __shfl_down_sync(0xFFFFFFFFu, tm, o);
        }
        if (lane == 0) { f_sum = ts; f_sq = tq; f_nleaf = tm; }
        if (lane == 31) f_cnt = incl;
    }
    __syncthreads();

    int nleaf = f_nleaf;
    if (nleaf < 10) {
        float4 zz = make_float4(0.f, 0.f, 0.f, 0.f);
        float4* so4 = (float4*)(scores + fb * NN);
        for (int i = tid; i < NN / 4; i += TPB) so4[i] = zz;
        if (tid == 0) { conf_out[fb] = 0.0f; g_done[fb] = 0; }
        return;
    }

    // gather chunk lists into globally compacted ascending order (global scratch)
    for (int c2 = warp; c2 < CPB; c2 += 8) {
        int cc = ccnt_s[c2];
        int dst = cpref[c2];
        for (int j = lane; j < cc; j += 32)
            g_selc[fb][dst + j] = g_sel[fb][c2 * PPC + j];
    }
    __syncthreads();

    const float* P = points + (size_t)fb * NN * 3;
    int cnt = f_cnt;
    int pc = cnt - 1;
    float sd = 0.0f, sd2 = 0.0f;
    for (int q = tid; q < pc; q += TPB) {
        int i1 = g_selc[fb][q], i2 = g_selc[fb][q + 1];
        float dx = P[i2 * 3 + 0] - P[i1 * 3 + 0];
        float dy = P[i2 * 3 + 1] - P[i1 * 3 + 1];
        float dz = P[i2 * 3 + 2] - P[i1 * 3 + 2];
        float d = sqrtf(dx * dx + dy * dy + dz * dz);
        sd += d; sd2 += d * d;
    }
    for (int o = 16; o; o >>= 1) {
        sd  += __shfl_down_sync(0xFFFFFFFFu, sd, o);
        sd2 += __shfl_down_sync(0xFFFFFFFFu, sd2, o);
    }
    if (lane == 0) { wsd[warp] = sd; wsd2[warp] = sd2; }
    __syncthreads();

    if (tid == 0) {
        float tsd = 0.f, tsd2 = 0.f;
#pragma unroll
        for (int w = 0; w < 8; w++) { tsd += wsd[w]; tsd2 += wsd2[w]; }
        float tsum = f_sum, tsq = f_sq;
        float nl = (float)nleaf;
        float mean = tsum / fmaxf(nl, 1.0f);
        float clarity = (tsq - 2.0f * mean * tsum + mean * mean * nl)
                        / fmaxf(nl - 1.0f, 1.0f);
        float pcf = (float)(pc > 0 ? pc : 0);
        float meand = tsd / fmaxf(pcf, 1.0f);
        float dvar = (tsd2 - 2.0f * meand * tsd + meand * meand * pcf)
                     / fmaxf(pcf - 1.0f, 1.0f);
        float cont = fminf(fmaxf(1.0f / (dvar + 1e-8f), 0.0f), 1.0f);
        cont = (cnt > 5) ? cont : 0.0f;
        float conf = fminf(fmaxf(clarity * cont, 0.0f), 1.0f);
        conf = (nleaf == 0) ? 0.0f : conf;
        conf_out[fb] = conf;
        g_done[fb] = 0;
    }
}

// ============================================================
// launch — single kernel, grid 128 (single wave), dynamic smem
// ============================================================
extern "C" void kernel_launch(void* const* d_in, const int* in_sizes, int n_in,
                              void* d_out, int out_size) {
    const float* points   = (const float*)d_in[0];
    const float* features = (const float*)d_in[1];
    const int*   mask     = (const int*)d_in[2];
    const float* W1 = (const float*)d_in[3];
    const float* b1 = (const float*)d_in[4];
    const float* W2 = (const float*)d_in[5];
    const float* b2 = (const float*)d_in[6];
    const float* W3 = (const float*)d_in[7];
    const float* b3 = (const float*)d_in[8];

    float* out_scores = (float*)d_out;                       // [B*N]
    float* out_feats  = out_scores + BB * NN;                // [B*N*F]
    float* out_conf   = out_feats + (size_t)BB * NN * FF;    // [B]

    static int attr_set = 0;
    if (!attr_set) {
        cudaFuncSetAttribute(mlp_mma_kernel,
                             cudaFuncAttributeMaxDynamicSharedMemorySize, DYN_BYTES);
        attr_set = 1;
    }

    mlp_mma_kernel<<<(BB * NN) / PPC, TPB, DYN_BYTES>>>(
        points, features, mask, W1, b1, W2, b2, W3, b3,
        out_scores, out_feats, out_conf);
}

// round 16
// speedup vs baseline: 1.9428x; 1.0360x over previous
#include <cuda_runtime.h>
#include <cuda_fp16.h>
#include <math.h>
#include <stdint.h>

#define BB 4
#define NN 8192
#define FF 64
#define H2 32
#define TPB 256           // threads per CTA = 8 warps; 1 point per thread
#define PPC 256           // points per CTA
#define CPB 32            // chunks (CTAs) per batch = 8192/256

#define XROW 88           // padded halves per X/W1 row (67 valid + bias + pad)
#define W2ROW 72          // padded halves per W2 row (64 valid)

// dynamic smem carve
#define SX_BYTES  (PPC * XROW * 2)          // 45056
#define SW1_OFF   SX_BYTES                  // 45056
#define SW2_OFF   (SW1_OFF + 64 * XROW * 2) // 56320
#define DYN_BYTES (SW2_OFF + 32 * W2ROW * 2)// 60928

// ---- scratch (static, no allocation) ----
__device__ float g_csum[BB * CPB];
__device__ float g_csq[BB * CPB];
__device__ int   g_ccnt[BB * CPB];
__device__ int   g_cmask[BB * CPB];
__device__ float4 g_selp[BB][NN];     // per-chunk compacted selected point coords
__device__ float4 g_selcp[BB][NN];    // globally compacted selected point coords
__device__ int   g_done[BB];          // zero-init; reset after each use

static __device__ __forceinline__ void mma16816(
    float& c0, float& c1, float& c2, float& c3,
    uint32_t a0, uint32_t a1, uint32_t a2, uint32_t a3,
    uint32_t b0, uint32_t b1)
{
    asm volatile(
        "mma.sync.aligned.m16n8k16.row.col.f32.f16.f16.f32 "
        "{%0,%1,%2,%3}, {%4,%5,%6,%7}, {%8,%9}, {%0,%1,%2,%3};"
        : "+f"(c0), "+f"(c1), "+f"(c2), "+f"(c3)
        : "r"(a0), "r"(a1), "r"(a2), "r"(a3), "r"(b0), "r"(b1));
}
static __device__ __forceinline__ uint32_t ldh2(const __half* p) {
    return *reinterpret_cast<const uint32_t*>(p);
}
static __device__ __forceinline__ uint32_t pack_relu(float a, float b) {
    __half2 h = __floats2half2_rn(fmaxf(a, 0.f), fmaxf(b, 0.f));
    return *reinterpret_cast<uint32_t*>(&h);
}

extern __shared__ __align__(16) char dynsmem[];

// ============================================================
// Single kernel: HMMA MLP 67->64->32->1 (+mask). W-first prologue,
// WARP-LOCAL X streaming (no block sync before MMA), coordinate-
// carrying compaction, last-CTA-per-batch finalize. Grid 128 = 1 wave.
// ============================================================
__global__ __launch_bounds__(TPB) void mlp_mma_kernel(
    const float* __restrict__ points, const float* __restrict__ features,
    const int* __restrict__ mask,
    const float* __restrict__ W1, const float* __restrict__ b1,
    const float* __restrict__ W2, const float* __restrict__ b2,
    const float* __restrict__ W3, const float* __restrict__ b3,
    float* __restrict__ scores, float* __restrict__ out_feats,
    float* __restrict__ conf_out)
{
    __half* sX  = reinterpret_cast<__half*>(dynsmem);
    __half* sW1 = reinterpret_cast<__half*>(dynsmem + SW1_OFF);
    __half* sW2 = reinterpret_cast<__half*>(dynsmem + SW2_OFF);

    __shared__ float sW3[H2], sb2[H2];
    __shared__ float sb3;
    __shared__ float rsum[8], rsq[8];
    __shared__ int rcnt[8], rmask[8], roff[8];
    __shared__ int cpref[CPB], ccnt_s[CPB];
    __shared__ float f_sum, f_sq;
    __shared__ int f_cnt, f_nleaf, s_last;
    __shared__ float wsd[8], wsd2[8];

    int tid = threadIdx.x;
    int lane = tid & 31, warp = tid >> 5;
    int g = lane >> 2, c = lane & 3;       // mma fragment coords

    int p = blockIdx.x * PPC + tid;
    int fb = p >> 13;

    // early latency-critical per-point loads
    const float* pp = points + (size_t)p * 3;
    float px = pp[0], py = pp[1], pz = pp[2];
    int m = mask[p];

    // ---- W prologue FIRST (small, L2-broadcast), then one sync ----
    for (int idx = tid; idx < 64 * (XROW / 2); idx += TPB) {
        int j = idx / (XROW / 2), k2 = idx % (XROW / 2);
        int cc = 2 * k2;
        float a  = (cc < 67) ? W1[j * 67 + cc] : ((cc == 67) ? b1[j] : 0.f);
        float bv = (cc + 1 < 67) ? W1[j * 67 + cc + 1] : ((cc + 1 == 67) ? b1[j] : 0.f);
        *reinterpret_cast<__half2*>(&sW1[j * XROW + cc]) = __floats2half2_rn(a, bv);
    }
    for (int idx = tid; idx < 32 * (W2ROW / 2); idx += TPB) {
        int j = idx / (W2ROW / 2), k2 = idx % (W2ROW / 2);
        int cc = 2 * k2;
        float a  = (cc < 64) ? W2[j * 64 + cc] : 0.f;
        float bv = (cc + 1 < 64) ? W2[j * 64 + cc + 1] : 0.f;
        *reinterpret_cast<__half2*>(&sW2[j * W2ROW + cc]) = __floats2half2_rn(a, bv);
    }
    if (tid < H2) { sb2[tid] = b2[tid]; sW3[tid] = W3[tid]; }
    if (tid == 0) sb3 = b3[0];
    __syncthreads();      // only block-wide sync before MMA (weights ready)

    // ---- WARP-LOCAL coalesced X streaming: warp w owns rows [32w,32w+32) ----
    {
        int pbase = blockIdx.x * PPC;
        const float4* f4 = (const float4*)(features + (size_t)pbase * FF);
        float4* o4 = (float4*)(out_feats + (size_t)pbase * FF);
#pragma unroll
        for (int k = 0; k < 16; k++) {
            int j = warp * 512 + k * 32 + lane;      // 32 consecutive float4/iter
            float4 v = f4[j];
            o4[j] = v;
            int row = j >> 4, col4 = j & 15;
            __half2* dst = reinterpret_cast<__half2*>(&sX[row * XROW + col4 * 4]);
            dst[0] = __floats2half2_rn(v.x, v.y);
            dst[1] = __floats2half2_rn(v.z, v.w);
        }
        // X tail columns 64..87 for own row (own warp's block)
        __half2* xr = reinterpret_cast<__half2*>(&sX[tid * XROW + 64]);
        xr[0] = __floats2half2_rn(px, py);
        xr[1] = __floats2half2_rn(pz, 1.0f);     // col 66 = z, col 67 = bias
#pragma unroll
        for (int i = 2; i < 12; i++) xr[i] = __floats2half2_rn(0.f, 0.f);
    }
    __syncwarp();        // warp-local: its MMA only reads its own 32 rows

    // ---- layer 1: per-warp H1[32x64] = X[32x80] @ W1^T, fp32 accum ----
    float acc[2][8][4];
#pragma unroll
    for (int M = 0; M < 2; M++)
#pragma unroll
        for (int j = 0; j < 8; j++)
#pragma unroll
            for (int q = 0; q < 4; q++) acc[M][j][q] = 0.f;

    int r0 = warp * 32 + g;
#pragma unroll
    for (int t = 0; t < 5; t++) {
        int k0 = 16 * t + 2 * c;
        uint32_t a[2][4];
#pragma unroll
        for (int M = 0; M < 2; M++) {
            int rr = r0 + 16 * M;
            a[M][0] = ldh2(&sX[rr * XROW + k0]);
            a[M][1] = ldh2(&sX[(rr + 8) * XROW + k0]);
            a[M][2] = ldh2(&sX[rr * XROW + k0 + 8]);
            a[M][3] = ldh2(&sX[(rr + 8) * XROW + k0 + 8]);
        }
#pragma unroll
        for (int j = 0; j < 8; j++) {
            int n = 8 * j + g;
            uint32_t b0 = ldh2(&sW1[n * XROW + k0]);
            uint32_t b1r = ldh2(&sW1[n * XROW + k0 + 8]);
            mma16816(acc[0][j][0], acc[0][j][1], acc[0][j][2], acc[0][j][3],
                     a[0][0], a[0][1], a[0][2], a[0][3], b0, b1r);
            mma16816(acc[1][j][0], acc[1][j][1], acc[1][j][2], acc[1][j][3],
                     a[1][0], a[1][1], a[1][2], a[1][3], b0, b1r);
        }
    }

    // ---- relu + repack C-frags into layer-2 A-frags (in registers) ----
    uint32_t a2f[2][4][4];
#pragma unroll
    for (int M = 0; M < 2; M++)
#pragma unroll
        for (int t2 = 0; t2 < 4; t2++) {
            a2f[M][t2][0] = pack_relu(acc[M][2 * t2][0],     acc[M][2 * t2][1]);
            a2f[M][t2][1] = pack_relu(acc[M][2 * t2][2],     acc[M][2 * t2][3]);
            a2f[M][t2][2] = pack_relu(acc[M][2 * t2 + 1][0], acc[M][2 * t2 + 1][1]);
            a2f[M][t2][3] = pack_relu(acc[M][2 * t2 + 1][2], acc[M][2 * t2 + 1][3]);
        }

    // ---- layer 2: H2[32x32] = H1[32x64] @ W2^T ----
    float acc2[2][4][4];
#pragma unroll
    for (int M = 0; M < 2; M++)
#pragma unroll
        for (int n = 0; n < 4; n++)
#pragma unroll
            for (int q = 0; q < 4; q++) acc2[M][n][q] = 0.f;
#pragma unroll
    for (int t2 = 0; t2 < 4; t2++) {
        int k0 = 16 * t2 + 2 * c;
#pragma unroll
        for (int n = 0; n < 4; n++) {
            int nn = 8 * n + g;
            uint32_t b0 = ldh2(&sW2[nn * W2ROW + k0]);
            uint32_t b1r = ldh2(&sW2[nn * W2ROW + k0 + 8]);
            mma16816(acc2[0][n][0], acc2[0][n][1], acc2[0][n][2], acc2[0][n][3],
                     a2f[0][t2][0], a2f[0][t2][1], a2f[0][t2][2], a2f[0][t2][3], b0, b1r);
            mma16816(acc2[1][n][0], acc2[1][n][1], acc2[1][n][2], acc2[1][n][3],
                     a2f[1][t2][0], a2f[1][t2][1], a2f[1][t2][2], a2f[1][t2][3], b0, b1r);
        }
    }

    // ---- stage h2 into dead X region (warp-local rows), f32 ----
#pragma unroll
    for (int M = 0; M < 2; M++) {
        int rr = r0 + 16 * M;
        float* h0 = reinterpret_cast<float*>(&sX[rr * XROW]);
        float* h8 = reinterpret_cast<float*>(&sX[(rr + 8) * XROW]);
#pragma unroll
        for (int n = 0; n < 4; n++) {
            int col = 8 * n + 2 * c;
            h0[col] = acc2[M][n][0]; h0[col + 1] = acc2[M][n][1];
            h8[col] = acc2[M][n][2]; h8[col + 1] = acc2[M][n][3];
        }
    }
    __syncwarp();

    // ---- layer 3 (fp32): this thread's row, +b2, relu, dot W3, sigmoid ----
    float score;
    {
        const float* hr = reinterpret_cast<const float*>(&sX[tid * XROW]);
        float z0 = 0.f, z1 = 0.f, z2 = 0.f, z3 = 0.f;
#pragma unroll
        for (int i = 0; i < H2; i += 4) {
            z0 += sW3[i]     * fmaxf(hr[i]     + sb2[i],     0.f);
            z1 += sW3[i + 1] * fmaxf(hr[i + 1] + sb2[i + 1], 0.f);
            z2 += sW3[i + 2] * fmaxf(hr[i + 2] + sb2[i + 2], 0.f);
            z3 += sW3[i + 3] * fmaxf(hr[i + 3] + sb2[i + 3], 0.f);
        }
        float z = sb3 + (z0 + z1) + (z2 + z3);
        float sv = 1.0f / (1.0f + expf(-z));
        score = (m != 0) ? sv : 0.0f;
    }
    scores[p] = score;

    // ---------- fused stats + coordinate-carrying compaction ----------
    bool selp = (score > 0.7f);
    unsigned int bal = __ballot_sync(0xFFFFFFFFu, selp);
    int wcnt = __popc(bal);
    int myoff = __popc(bal & ((1u << lane) - 1u));

    float sum = score, sq = score * score;
    int mc = (m != 0);
    for (int o = 16; o; o >>= 1) {
        sum += __shfl_down_sync(0xFFFFFFFFu, sum, o);
        sq  += __shfl_down_sync(0xFFFFFFFFu, sq, o);
        mc  += __shfl_down_sync(0xFFFFFFFFu, mc, o);
    }
    if (lane == 0) { rsum[warp] = sum; rsq[warp] = sq; rcnt[warp] = wcnt; rmask[warp] = mc; }
    __syncthreads();
    if (tid == 0) {
        float ts = 0.f, tq = 0.f; int tc = 0, tm = 0;
#pragma unroll
        for (int w = 0; w < 8; w++) {
            roff[w] = tc;
            ts += rsum[w]; tq += rsq[w]; tc += rcnt[w]; tm += rmask[w];
        }
        int cid = blockIdx.x;
        g_csum[cid] = ts; g_csq[cid] = tq; g_ccnt[cid] = tc; g_cmask[cid] = tm;
    }
    __syncthreads();
    if (selp) {
        int chunk = blockIdx.x & (CPB - 1);
        g_selp[fb][chunk * PPC + roff[warp] + myoff] = make_float4(px, py, pz, 0.f);
    }

    // ---------- last-CTA-per-batch finalize ----------
    __threadfence();
    __syncthreads();
    if (tid == 0) {
        int done = atomicAdd(&g_done[fb], 1);
        s_last = (done == CPB - 1) ? 1 : 0;
    }
    __syncthreads();
    if (!s_last) return;
    __threadfence();

    // warp 0: reduce + prefix the 32 chunk records of batch fb
    if (warp == 0) {
        int cid = fb * CPB + lane;
        float cs = g_csum[cid], cq = g_csq[cid];
        int cc = g_ccnt[cid], cm = g_cmask[cid];
        ccnt_s[lane] = cc;
        int incl = cc;
        for (int o = 1; o < 32; o <<= 1) {
            int t = __shfl_up_sync(0xFFFFFFFFu, incl, o);
            if (lane >= o) incl += t;
        }
        cpref[lane] = incl - cc;
        float ts = cs, tq = cq; int tm = cm;
        for (int o = 16; o; o >>= 1) {
            ts += __shfl_down_sync(0xFFFFFFFFu, ts, o);
            tq += __shfl_down_sync(0xFFFFFFFFu, tq, o);
            tm += __shfl_down_sync(0xFFFFFFFFu, tm, o);
        }
        if (lane == 0) { f_sum = ts; f_sq = tq; f_nleaf = tm; }
        if (lane == 31) f_cnt = incl;
    }
    __syncthreads();

    int nleaf = f_nleaf;
    if (nleaf < 10) {
        float4 zz = make_float4(0.f, 0.f, 0.f, 0.f);
        float4* so4 = (float4*)(scores + fb * NN);
        for (int i = tid; i < NN / 4; i += TPB) so4[i] = zz;
        if (tid == 0) { conf_out[fb] = 0.0f; g_done[fb] = 0; }
        return;
    }

    // gather chunk coord lists into contiguous ascending order
    for (int c2 = warp; c2 < CPB; c2 += 8) {
        int cc = ccnt_s[c2];
        int dst = cpref[c2];
        for (int j = lane; j < cc; j += 32)
            g_selcp[fb][dst + j] = g_selp[fb][c2 * PPC + j];
    }
    __syncthreads();

    int cnt = f_cnt;
    int pc = cnt - 1;
    float sd = 0.0f, sd2 = 0.0f;
    for (int q = tid; q < pc; q += TPB) {
        float4 A = g_selcp[fb][q], Bv = g_selcp[fb][q + 1];
        float dx = Bv.x - A.x, dy = Bv.y - A.y, dz = Bv.z - A.z;
        float d = sqrtf(dx * dx + dy * dy + dz * dz);
        sd += d; sd2 += d * d;
    }
    for (int o = 16; o; o >>= 1) {
        sd  += __shfl_down_sync(0xFFFFFFFFu, sd, o);
        sd2 += __shfl_down_sync(0xFFFFFFFFu, sd2, o);
    }
    if (lane == 0) { wsd[warp] = sd; wsd2[warp] = sd2; }
    __syncthreads();

    if (tid == 0) {
        float tsd = 0.f, tsd2 = 0.f;
#pragma unroll
        for (int w = 0; w < 8; w++) { tsd += wsd[w]; tsd2 += wsd2[w]; }
        float tsum = f_sum, tsq = f_sq;
        float nl = (float)nleaf;
        float mean = tsum / fmaxf(nl, 1.0f);
        float clarity = (tsq - 2.0f * mean * tsum + mean * mean * nl)
                        / fmaxf(nl - 1.0f, 1.0f);
        float pcf = (float)(pc > 0 ? pc : 0);
        float meand = tsd / fmaxf(pcf, 1.0f);
        float dvar = (tsd2 - 2.0f * meand * tsd + meand * meand * pcf)
                     / fmaxf(pcf - 1.0f, 1.0f);
        float cont = fminf(fmaxf(1.0f / (dvar + 1e-8f), 0.0f), 1.0f);
        cont = (cnt > 5) ? cont : 0.0f;
        float conf = fminf(fmaxf(clarity * cont, 0.0f), 1.0f);
        conf = (nleaf == 0) ? 0.0f : conf;
        conf_out[fb] = conf;
        g_done[fb] = 0;
    }
}

// ============================================================
// launch — single kernel, grid 128 (single wave), dynamic smem
// ============================================================
extern "C" void kernel_launch(void* const* d_in, const int* in_sizes, int n_in,
                              void* d_out, int out_size) {
    const float* points   = (const float*)d_in[0];
    const float* features = (const float*)d_in[1];
    const int*   mask     = (const int*)d_in[2];
    const float* W1 = (const float*)d_in[3];
    const float* b1 = (const float*)d_in[4];
    const float* W2 = (const float*)d_in[5];
    const float* b2 = (const float*)d_in[6];
    const float* W3 = (const float*)d_in[7];
    const float* b3 = (const float*)d_in[8];

    float* out_scores = (float*)d_out;                       // [B*N]
    float* out_feats  = out_scores + BB * NN;                // [B*N*F]
    float* out_conf   = out_feats + (size_t)BB * NN * FF;    // [B]

    static int attr_set = 0;
    if (!attr_set) {
        cudaFuncSetAttribute(mlp_mma_kernel,
                             cudaFuncAttributeMaxDynamicSharedMemorySize, DYN_BYTES);
        attr_set = 1;
    }

    mlp_mma_kernel<<<(BB * NN) / PPC, TPB, DYN_BYTES>>>(
        points, features, mask, W1, b1, W2, b2, W3, b3,
        out_scores, out_feats, out_conf);
}